// round 8
// baseline (speedup 1.0000x reference)
#include <cuda_runtime.h>
#include <cuda_bf16.h>
#include <math.h>
#include <stdint.h>

// ---------------- problem constants ----------------
#define B_   32
#define TW   40
#define N_   50
#define CIN  2
#define H_   128
#define CO_  64
#define E_   800
#define T1   38            // after tconv1
#define T2T  36            // after tconv2
#define NG   (B_*T1)       // 1216 graphs
#define J_   (N_*CO_)      // 3200
#define OC3  128           // conv3 out channels
#define M_CH (NG*N_)       // 60800 rows, cheb GEMM
#define M_TC (B_*T2T*N_)   // 57600 rows, tconv2 GEMM
#define NH_  (N_*H_)       // 6400

// ---------------- scratch (static device, no allocation) ----------------
__device__ float g_T0[NG*NH_];              // 7.78M  (tf32-rounded)
__device__ float g_TX[NG*2*NH_];            // 15.6M  [g][k-1][n][f] (tf32-rounded)
__device__ float g_G [NG*NH_];              // 7.78M  (tf32-rounded)
__device__ float g_Wch[384*128];            // rounded cheb weights
__device__ float g_Wt2[384*192];            // packed+rounded tconv2 weights
__device__ float g_gate[(size_t)M_TC*192];  // 11.06M
__device__ float g_T2[(size_t)M_TC*CO_];    // 3.69M
__device__ float g_V [B_*3*J_];
__device__ float g_bnpart[N_*16*2];
__device__ float g_scale[N_], g_shift[N_];
__device__ float g_pooled[B_*OC3];

// ---------------- helpers ----------------
__device__ __forceinline__ uint32_t f2tf(float f) {
    uint32_t u; asm("cvt.rna.tf32.f32 %0, %1;" : "=r"(u) : "f"(f)); return u;
}
__device__ __forceinline__ float rtf(float f) { return __uint_as_float(f2tf(f)); }
__device__ __forceinline__ void mma_tf32(float* c, const uint32_t* a, const uint32_t* b) {
    asm volatile("mma.sync.aligned.m16n8k8.row.col.f32.tf32.tf32.f32 "
        "{%0,%1,%2,%3}, {%4,%5,%6,%7}, {%8,%9}, {%0,%1,%2,%3};"
        : "+f"(c[0]), "+f"(c[1]), "+f"(c[2]), "+f"(c[3])
        : "r"(a[0]), "r"(a[1]), "r"(a[2]), "r"(a[3]), "r"(b[0]), "r"(b[1]));
}
__device__ __forceinline__ void cp16(uint32_t dst, const void* src) {
    asm volatile("cp.async.cg.shared.global [%0], [%1], 16;" :: "r"(dst), "l"(src));
}

// ============================================================
// K1: tconv1  X(B,40,50,2) -> T0(B,38,50,128), tf32-rounded store
// ============================================================
__global__ void k_tconv1(const float* __restrict__ X,
                         const float* __restrict__ w1, const float* __restrict__ b1,
                         const float* __restrict__ w2, const float* __restrict__ b2,
                         const float* __restrict__ w3, const float* __restrict__ b3)
{
    int bn = blockIdx.x;
    int b = bn / N_, n = bn % N_;
    int h = threadIdx.x;

    __shared__ float xs[TW*CIN];
    for (int i = threadIdx.x; i < TW*CIN; i += blockDim.x) {
        int t = i >> 1, c = i & 1;
        xs[i] = X[((b*TW + t)*N_ + n)*CIN + c];
    }
    float W1[6], W2[6], W3[6];
#pragma unroll
    for (int q = 0; q < 6; q++) {
        W1[q] = w1[q*H_ + h]; W2[q] = w2[q*H_ + h]; W3[q] = w3[q*H_ + h];
    }
    float B1 = b1[h], B2 = b2[h], B3 = b3[h];
    __syncthreads();

    for (int t = 0; t < T1; t++) {
        float P = B1, Q = B2, R = B3;
#pragma unroll
        for (int k = 0; k < 3; k++)
#pragma unroll
            for (int c = 0; c < 2; c++) {
                float v = xs[(t+k)*2 + c];
                int q = k*2 + c;
                P += v*W1[q]; Q += v*W2[q]; R += v*W3[q];
            }
        float s = 1.f/(1.f + expf(-Q));
        float o = P*s + R;
        o = o > 0.f ? o : 0.f;
        g_T0[((size_t)(b*T1 + t)*N_ + n)*H_ + h] = rtf(o);
    }
}

// ============================================================
// K2: Chebyshev propagation, column-split: 2 blocks per graph,
// each handles 64 of the 128 feature columns. FFMA, register-blocked.
// smem floats: A[64x50=3200] | x0[50x68] | t1s[50x68] | dis[64] | deg[64]
// ============================================================
#define CSTR 68
__global__ __launch_bounds__(256) void k_cheb_prop(const int* __restrict__ EI)
{
    extern __shared__ float sm[];
    float* A   = sm;                // 64 rows x 50 (rows 50..63 zero)
    float* x0  = sm + 3200;         // 50 x CSTR (64 cols used)
    float* t1s = x0 + 50*CSTR;
    float* dis = t1s + 50*CSTR;
    int*   deg = (int*)(dis + 64);

    const int gb = blockIdx.x;
    const int g = gb >> 1, half = gb & 1;
    const int coff = half * 64;
    const int b = g / T1, t = g % T1;
    const int tid = threadIdx.x;     // 256

    for (int i = tid; i < 3200; i += 256) A[i] = 0.f;
    if (tid < 64) deg[tid] = 0;
    __syncthreads();

    const int* rows = EI + ((size_t)(b*TW + t)*2 + 0)*E_;
    const int* cols = EI + ((size_t)(b*TW + t)*2 + 1)*E_;
    for (int e = tid; e < E_; e += 256) atomicAdd(&deg[rows[e]], 1);
    __syncthreads();
    if (tid < N_) { int d = deg[tid]; dis[tid] = d > 0 ? rsqrtf((float)d) : 0.f; }
    __syncthreads();
    for (int e = tid; e < E_; e += 256) {
        int r = rows[e], c = cols[e];
        atomicAdd(&A[r*N_ + c], -dis[r]*dis[c]);
    }

    // load x0: 50 rows x 64 cols (this block's half)
    for (int i = tid; i < 50*16; i += 256) {
        int r = i >> 4, c4 = (i & 15) << 2;
        *(float4*)(x0 + r*CSTR + c4) =
            *(const float4*)(g_T0 + (size_t)g*NH_ + r*H_ + coff + c4);
    }
    __syncthreads();

    const int tx = tid & 15;     // float4 col group (0..15 -> 64 cols)
    const int ng = tid >> 4;     // 0..15 -> rows ng+16i

    // ---- t1 = A @ x0 ----
    {
        float4 acc[4];
#pragma unroll
        for (int i = 0; i < 4; i++) acc[i] = make_float4(0,0,0,0);
        for (int m = 0; m < N_; m++) {
            float4 xv = *(const float4*)(x0 + m*CSTR + tx*4);
#pragma unroll
            for (int i = 0; i < 4; i++) {
                float a = A[(ng + 16*i)*N_ + m];   // rows >=50 are zero
                acc[i].x += a*xv.x; acc[i].y += a*xv.y;
                acc[i].z += a*xv.z; acc[i].w += a*xv.w;
            }
        }
#pragma unroll
        for (int i = 0; i < 4; i++) {
            int n = ng + 16*i;
            if (n < N_) {
                *(float4*)(t1s + n*CSTR + tx*4) = acc[i];
                float4 r = make_float4(rtf(acc[i].x), rtf(acc[i].y),
                                       rtf(acc[i].z), rtf(acc[i].w));
                *(float4*)(g_TX + (size_t)g*2*NH_ + n*H_ + coff + tx*4) = r;
            }
        }
    }
    __syncthreads();

    // ---- t2 = 2*A@t1 - x0 ----
    {
        float4 acc[4];
#pragma unroll
        for (int i = 0; i < 4; i++) acc[i] = make_float4(0,0,0,0);
        for (int m = 0; m < N_; m++) {
            float4 xv = *(const float4*)(t1s + m*CSTR + tx*4);
#pragma unroll
            for (int i = 0; i < 4; i++) {
                float a = A[(ng + 16*i)*N_ + m];
                acc[i].x += a*xv.x; acc[i].y += a*xv.y;
                acc[i].z += a*xv.z; acc[i].w += a*xv.w;
            }
        }
#pragma unroll
        for (int i = 0; i < 4; i++) {
            int n = ng + 16*i;
            if (n < N_) {
                float4 xo = *(const float4*)(x0 + n*CSTR + tx*4);
                float4 r;
                r.x = rtf(2.f*acc[i].x - xo.x); r.y = rtf(2.f*acc[i].y - xo.y);
                r.z = rtf(2.f*acc[i].z - xo.z); r.w = rtf(2.f*acc[i].w - xo.w);
                *(float4*)(g_TX + (size_t)g*2*NH_ + NH_ + n*H_ + coff + tx*4) = r;
            }
        }
    }
}

// ============================================================
// K3a: pack+round tconv2 weights.  K3b: round cheb weights.
// ============================================================
__global__ void k_prepW(const float* __restrict__ w1, const float* __restrict__ w2,
                        const float* __restrict__ w3)
{
    int i = blockIdx.x*256 + threadIdx.x;   // over 384*64
    if (i < 384*64) {
        int kt = i >> 6, co = i & 63;
        g_Wt2[kt*192 + co]       = rtf(w1[i]);
        g_Wt2[kt*192 + 64 + co]  = rtf(w2[i]);
        g_Wt2[kt*192 + 128 + co] = rtf(w3[i]);
    }
}
__global__ void k_cvtCh(const float* __restrict__ chw)
{
    int i = blockIdx.x*256 + threadIdx.x;
    if (i < 384*128) g_Wch[i] = rtf(chw[i]);
}

// ============================================================
// K4: tf32 MMA GEMM, cp.async double-buffered.
// BM=128, BN=64, BK=32, 256 threads (8 warps 4x2)
// MODE 0: A = [T0 | TX] (M_CH x 384), B = g_Wch (384x128), bias+relu -> g_G (rounded)
// MODE 1: A = g_G taps (M_TC x 384),  B = g_Wt2 (384x192), raw -> g_gate
// ============================================================
#define AST 36
#define BST 72
#define NKI 12

#define ISSUE_LOADS(ST, K0) do {                                              \
    int kk_ = (K0) >> 7, fb_ = (K0) & 127;                                    \
    _Pragma("unroll")                                                         \
    for (int j_ = 0; j_ < 4; j_++) {                                          \
        const float* s_;                                                      \
        if (MODE == 0)                                                        \
            s_ = (kk_ == 0) ? (g_T0 + ab0[j_] + fb_ + ac4)                    \
                            : (g_TX + abX[j_] + (size_t)(kk_-1)*NH_ + fb_ + ac4); \
        else                                                                  \
            s_ = g_G + ab0[j_] + (size_t)kk_*NH_ + fb_ + ac4;                 \
        cp16((uint32_t)__cvta_generic_to_shared(&As[ST][arow + j_*32][ac4]), s_); \
    }                                                                         \
    _Pragma("unroll")                                                         \
    for (int j_ = 0; j_ < 2; j_++) {                                          \
        int row_ = brow + j_*16;                                              \
        cp16((uint32_t)__cvta_generic_to_shared(&Bs[ST][row_][bc4]),          \
             Bmat + (size_t)((K0) + row_)*BNS + nb + bc4);                    \
    }                                                                         \
    asm volatile("cp.async.commit_group;");                                   \
} while (0)

template<int MODE>
__global__ __launch_bounds__(256) void k_gemm(const float* __restrict__ bias)
{
    __shared__ float As[2][128][AST];
    __shared__ float Bs[2][32][BST];

    const int tid  = threadIdx.x;
    const int bm   = blockIdx.x;
    const int nb   = blockIdx.y * 64;
    const int warp = tid >> 5, lane = tid & 31;
    const int wm = (warp & 3) * 32, wn = (warp >> 2) * 32;
    const int g4 = lane >> 2, tg = lane & 3;

    const int BNS = (MODE == 0) ? 128 : 192;
    const float* Bmat = (MODE == 0) ? g_Wch : g_Wt2;

    const int arow = tid >> 3, ac4 = (tid & 7) << 2;
    const int brow = tid >> 4, bc4 = (tid & 15) << 2;

    size_t ab0[4], abX[4];
#pragma unroll
    for (int j = 0; j < 4; j++) {
        int R = bm*128 + arow + j*32;
        if (MODE == 0) {
            int g = R / N_, n = R - g*N_;
            ab0[j] = (size_t)g*NH_ + (size_t)n*H_;
            abX[j] = (size_t)g*2*NH_ + (size_t)n*H_;
        } else {
            int b = R / (T2T*N_);
            int rem = R - b*(T2T*N_);
            int t = rem / N_, n = rem - t*N_;
            ab0[j] = ((size_t)(b*T1 + t)*N_ + n)*H_;
            abX[j] = 0;
        }
    }

    float acc[2][4][4];
#pragma unroll
    for (int mt = 0; mt < 2; mt++)
#pragma unroll
        for (int nt = 0; nt < 4; nt++)
#pragma unroll
            for (int q = 0; q < 4; q++) acc[mt][nt][q] = 0.f;

    ISSUE_LOADS(0, 0);

    for (int it = 0; it < NKI; it++) {
        const int st = it & 1;
        if (it + 1 < NKI) {
            ISSUE_LOADS(st ^ 1, (it + 1) * 32);
            asm volatile("cp.async.wait_group 1;");
        } else {
            asm volatile("cp.async.wait_group 0;");
        }
        __syncthreads();

#pragma unroll
        for (int kt = 0; kt < 32; kt += 8) {
            uint32_t af[2][4], bf[4][2];
#pragma unroll
            for (int mt = 0; mt < 2; mt++) {
                int m = wm + mt*16;
                af[mt][0] = __float_as_uint(As[st][m + g4    ][kt + tg]);
                af[mt][1] = __float_as_uint(As[st][m + g4 + 8][kt + tg]);
                af[mt][2] = __float_as_uint(As[st][m + g4    ][kt + tg + 4]);
                af[mt][3] = __float_as_uint(As[st][m + g4 + 8][kt + tg + 4]);
            }
#pragma unroll
            for (int nt = 0; nt < 4; nt++) {
                bf[nt][0] = __float_as_uint(Bs[st][kt + tg    ][wn + nt*8 + g4]);
                bf[nt][1] = __float_as_uint(Bs[st][kt + tg + 4][wn + nt*8 + g4]);
            }
#pragma unroll
            for (int mt = 0; mt < 2; mt++)
#pragma unroll
                for (int nt = 0; nt < 4; nt++)
                    mma_tf32(acc[mt][nt], af[mt], bf[nt]);
        }
        __syncthreads();
    }

    // epilogue
#pragma unroll
    for (int mt = 0; mt < 2; mt++) {
        int r0 = bm*128 + wm + mt*16 + g4;
#pragma unroll
        for (int nt = 0; nt < 4; nt++) {
            int c = nb + wn + nt*8 + tg*2;
            float v0 = acc[mt][nt][0], v1 = acc[mt][nt][1];
            float v2 = acc[mt][nt][2], v3 = acc[mt][nt][3];
            if (MODE == 0) {
                float bx = bias[c], by = bias[c+1];
                v0 += bx; v1 += by; v2 += bx; v3 += by;
                v0 = v0 > 0.f ? rtf(v0) : 0.f; v1 = v1 > 0.f ? rtf(v1) : 0.f;
                v2 = v2 > 0.f ? rtf(v2) : 0.f; v3 = v3 > 0.f ? rtf(v3) : 0.f;
                *(float2*)(g_G + (size_t)r0*128 + c)      = make_float2(v0, v1);
                *(float2*)(g_G + (size_t)(r0+8)*128 + c)  = make_float2(v2, v3);
            } else {
                *(float2*)(g_gate + (size_t)r0*192 + c)     = make_float2(v0, v1);
                *(float2*)(g_gate + (size_t)(r0+8)*192 + c) = make_float2(v2, v3);
            }
        }
    }
}

// ============================================================
// K5: tconv2 gate epilogue: relu(P*sig(Q)+R) -> g_T2
// ============================================================
__global__ void k_tc2epi(const float* __restrict__ b1, const float* __restrict__ b2,
                         const float* __restrict__ b3)
{
    int idx = blockIdx.x*256 + threadIdx.x;      // over M_TC*64
    if (idx >= M_TC*CO_) return;
    int row = idx >> 6, co = idx & 63;
    const float* gr = g_gate + (size_t)row*192;
    float P = gr[co] + b1[co];
    float Q = gr[64 + co] + b2[co];
    float R = gr[128 + co] + b3[co];
    float s = 1.f/(1.f + expf(-Q));
    float o = P*s + R;
    g_T2[idx] = o > 0.f ? o : 0.f;
}

// ============================================================
// K6: BN partial sums  grid(50,16), then finalize
// ============================================================
__global__ void k_bnpart()
{
    int n = blockIdx.x, ch = blockIdx.y;
    int tid = threadIdx.x;                       // 128
    float s = 0.f, s2 = 0.f;
    for (int i = tid; i < 72*64; i += 128) {
        int row = ch*72 + (i >> 6);
        int co = i & 63;
        float v = g_T2[((size_t)row*N_ + n)*CO_ + co];
        s += v; s2 += v*v;
    }
    __shared__ float red[256];
    red[tid] = s; red[128 + tid] = s2;
    __syncthreads();
    for (int st = 64; st > 0; st >>= 1) {
        if (tid < st) { red[tid] += red[tid+st]; red[128+tid] += red[128+tid+st]; }
        __syncthreads();
    }
    if (tid == 0) {
        g_bnpart[(n*16 + ch)*2]     = red[0];
        g_bnpart[(n*16 + ch)*2 + 1] = red[128];
    }
}

__global__ void k_bnfin(const float* __restrict__ gamma, const float* __restrict__ beta)
{
    int n = threadIdx.x;
    if (n >= N_) return;
    float s = 0.f, s2 = 0.f;
    for (int ch = 0; ch < 16; ch++) {
        s  += g_bnpart[(n*16 + ch)*2];
        s2 += g_bnpart[(n*16 + ch)*2 + 1];
    }
    const float TOT = (float)(B_*T2T*CO_);
    float mean = s / TOT;
    float var  = s2 / TOT - mean*mean;
    float rstd = rsqrtf(var + 1e-5f);
    float sc = gamma[n]*rstd;
    g_scale[n] = sc;
    g_shift[n] = beta[n] - mean*sc;
}

// ============================================================
// K7: build V[b][k][j]
// ============================================================
__global__ void k_vprep()
{
    int b = blockIdx.x;
    int j = blockIdx.y*256 + threadIdx.x;
    if (j >= J_) return;
    int n = j / CO_;
    float sc = g_scale[n], sh = g_shift[n];
    const float* base = g_T2 + (size_t)b*T2T*J_ + j;
    float TS = 0.f, v0 = 0.f, v1 = 0.f, v34 = 0.f, v35 = 0.f;
    for (int t = 0; t < T2T; t++) {
        float x = base[(size_t)t*J_]*sc + sh;
        TS += x;
        if (t == 0)  v0 = x;
        if (t == 1)  v1 = x;
        if (t == 34) v34 = x;
        if (t == 35) v35 = x;
    }
    g_V[((size_t)b*3 + 0)*J_ + j] = TS - v34 - v35;
    g_V[((size_t)b*3 + 1)*J_ + j] = TS - v0  - v35;
    g_V[((size_t)b*3 + 2)*J_ + j] = TS - v0  - v1;
}

// ============================================================
// K8: pooled[b,o] = c3b[o] + (1/34)*dot(conv3_w[o], V[b])
// ============================================================
__global__ void k_pooled(const float* __restrict__ c3w, const float* __restrict__ c3b)
{
    int o = blockIdx.x;
    int b = blockIdx.y;
    int tid = threadIdx.x;
    const float* w = c3w + (size_t)o*3*J_;
    const float* v = g_V + (size_t)b*3*J_;
    float s = 0.f;
    for (int i = tid; i < 3*J_; i += 256) s += w[i]*v[i];
    __shared__ float red[256];
    red[tid] = s; __syncthreads();
    for (int st = 128; st > 0; st >>= 1) {
        if (tid < st) red[tid] += red[tid+st];
        __syncthreads();
    }
    if (tid == 0) g_pooled[b*OC3 + o] = c3b[o] + red[0]*(1.f/34.f);
}

// ============================================================
// K9: out[b,j] = f1_b[j] + sum_o pooled[b,o]*f1_w[o,j]
// ============================================================
__global__ void k_fc(const float* __restrict__ f1w, const float* __restrict__ f1b,
                     float* __restrict__ out)
{
    int b = blockIdx.y;
    int j = blockIdx.x*128 + threadIdx.x;
    __shared__ float ps[OC3];
    ps[threadIdx.x] = g_pooled[b*OC3 + threadIdx.x];
    __syncthreads();
    float s = f1b[j];
#pragma unroll 4
    for (int o = 0; o < OC3; o++) s += ps[o]*f1w[(size_t)o*J_ + j];
    out[(size_t)b*J_ + j] = s;
}

// ============================================================
// host launcher
// ============================================================
extern "C" void kernel_launch(void* const* d_in, const int* in_sizes, int n_in,
                              void* d_out, int out_size)
{
    const float *X=0,*w11=0,*b11=0,*w12=0,*b12=0,*w13=0,*b13=0;
    const float *chw=0,*chb=0;
    const float *w21=0,*b21=0,*w22=0,*b22=0,*w23=0,*b23=0;
    const float *gamma=0,*beta=0,*c3w=0,*c3b=0,*f1w=0,*f1b=0;
    const int *ei=0;
    int c768=0, c128=0, c24576=0, c64=0, c50=0;
    for (int i = 0; i < n_in; i++) {
        int s = in_sizes[i];
        const void* p = d_in[i];
        switch (s) {
            case 128000:  X = (const float*)p; break;
            case 2048000: ei = (const int*)p; break;
            case 768:
                if (c768==0) w11=(const float*)p; else if (c768==1) w12=(const float*)p; else w13=(const float*)p;
                c768++; break;
            case 128:
                if (c128==0) b11=(const float*)p; else if (c128==1) b12=(const float*)p;
                else if (c128==2) b13=(const float*)p; else if (c128==3) chb=(const float*)p;
                else c3b=(const float*)p;
                c128++; break;
            case 49152:   chw = (const float*)p; break;
            case 24576:
                if (c24576==0) w21=(const float*)p; else if (c24576==1) w22=(const float*)p; else w23=(const float*)p;
                c24576++; break;
            case 64:
                if (c64==0) b21=(const float*)p; else if (c64==1) b22=(const float*)p; else b23=(const float*)p;
                c64++; break;
            case 50:
                if (c50==0) gamma=(const float*)p; else beta=(const float*)p;
                c50++; break;
            case 1228800: c3w = (const float*)p; break;
            case 409600:  f1w = (const float*)p; break;
            case 3200:    f1b = (const float*)p; break;
            default: break;
        }
    }
    float* out = (float*)d_out;

    static const int PROP_SMEM = (3200 + 2*50*CSTR + 64 + 64) * 4;  // 40,512 B
    cudaFuncSetAttribute(k_cheb_prop, cudaFuncAttributeMaxDynamicSharedMemorySize, PROP_SMEM);

    k_tconv1   <<<B_*N_, 128>>>(X, w11, b11, w12, b12, w13, b13);
    k_prepW    <<<(384*64 + 255)/256, 256>>>(w21, w22, w23);
    k_cvtCh    <<<(384*128 + 255)/256, 256>>>(chw);
    k_cheb_prop<<<NG*2, 256, PROP_SMEM>>>(ei);
    k_gemm<0>  <<<dim3(M_CH/128, 2), 256>>>(chb);
    k_gemm<1>  <<<dim3(M_TC/128, 3), 256>>>(nullptr);
    k_tc2epi   <<<(M_TC*CO_ + 255)/256, 256>>>(b21, b22, b23);
    k_bnpart   <<<dim3(N_, 16), 128>>>();
    k_bnfin    <<<1, 64>>>(gamma, beta);
    k_vprep    <<<dim3(B_, (J_+255)/256), 256>>>();
    k_pooled   <<<dim3(OC3, B_), 256>>>(c3w, c3b);
    k_fc       <<<dim3(J_/128, B_), 128>>>(f1w, f1b, out);
}

// round 9
// speedup vs baseline: 1.0237x; 1.0237x over previous
#include <cuda_runtime.h>
#include <cuda_bf16.h>
#include <math.h>
#include <stdint.h>

// ---------------- problem constants ----------------
#define B_   32
#define TW   40
#define N_   50
#define CIN  2
#define H_   128
#define CO_  64
#define E_   800
#define T1   38            // after tconv1
#define T2T  36            // after tconv2
#define NG   (B_*T1)       // 1216 graphs
#define J_   (N_*CO_)      // 3200
#define OC3  128           // conv3 out channels
#define M_CH (NG*N_)       // 60800 rows, cheb GEMM
#define M_TC (B_*T2T*N_)   // 57600 rows, tconv2 GEMM
#define NH_  (N_*H_)       // 6400

// ---------------- scratch (static device, no allocation) ----------------
__device__ float g_T0[NG*NH_];              // 7.78M  (tf32-rounded)
__device__ float g_TX[NG*2*NH_];            // 15.6M  [g][k-1][n][f] (tf32-rounded)
__device__ float g_G [NG*NH_];              // 7.78M  (tf32-rounded)
__device__ float g_Wch[384*128];            // rounded cheb weights
__device__ float g_Wt2[384*192];            // packed+rounded tconv2 weights
__device__ float g_gate[(size_t)M_TC*192];  // 11.06M
__device__ float g_T2[(size_t)M_TC*CO_];    // 3.69M
__device__ float g_V [B_*3*J_];
__device__ float g_bnpart[N_*16*2];
__device__ float g_scale[N_], g_shift[N_];
__device__ float g_pooled[B_*OC3];

// ---------------- helpers ----------------
__device__ __forceinline__ uint32_t f2tf(float f) {
    uint32_t u; asm("cvt.rna.tf32.f32 %0, %1;" : "=r"(u) : "f"(f)); return u;
}
__device__ __forceinline__ float rtf(float f) { return __uint_as_float(f2tf(f)); }
__device__ __forceinline__ void mma_tf32(float* c, const uint32_t* a, const uint32_t* b) {
    asm volatile("mma.sync.aligned.m16n8k8.row.col.f32.tf32.tf32.f32 "
        "{%0,%1,%2,%3}, {%4,%5,%6,%7}, {%8,%9}, {%0,%1,%2,%3};"
        : "+f"(c[0]), "+f"(c[1]), "+f"(c[2]), "+f"(c[3])
        : "r"(a[0]), "r"(a[1]), "r"(a[2]), "r"(a[3]), "r"(b[0]), "r"(b[1]));
}
__device__ __forceinline__ void cp16(uint32_t dst, const void* src) {
    asm volatile("cp.async.cg.shared.global [%0], [%1], 16;" :: "r"(dst), "l"(src));
}

// ============================================================
// K1: tconv1  X(B,40,50,2) -> T0(B,38,50,128), tf32-rounded store
// ============================================================
__global__ void k_tconv1(const float* __restrict__ X,
                         const float* __restrict__ w1, const float* __restrict__ b1,
                         const float* __restrict__ w2, const float* __restrict__ b2,
                         const float* __restrict__ w3, const float* __restrict__ b3)
{
    int bn = blockIdx.x;
    int b = bn / N_, n = bn % N_;
    int h = threadIdx.x;

    __shared__ float xs[TW*CIN];
    for (int i = threadIdx.x; i < TW*CIN; i += blockDim.x) {
        int t = i >> 1, c = i & 1;
        xs[i] = X[((b*TW + t)*N_ + n)*CIN + c];
    }
    float W1[6], W2[6], W3[6];
#pragma unroll
    for (int q = 0; q < 6; q++) {
        W1[q] = w1[q*H_ + h]; W2[q] = w2[q*H_ + h]; W3[q] = w3[q*H_ + h];
    }
    float B1 = b1[h], B2 = b2[h], B3 = b3[h];
    __syncthreads();

    for (int t = 0; t < T1; t++) {
        float P = B1, Q = B2, R = B3;
#pragma unroll
        for (int k = 0; k < 3; k++)
#pragma unroll
            for (int c = 0; c < 2; c++) {
                float v = xs[(t+k)*2 + c];
                int q = k*2 + c;
                P += v*W1[q]; Q += v*W2[q]; R += v*W3[q];
            }
        float s = 1.f/(1.f + expf(-Q));
        float o = P*s + R;
        o = o > 0.f ? o : 0.f;
        g_T0[((size_t)(b*T1 + t)*N_ + n)*H_ + h] = rtf(o);
    }
}

// ============================================================
// K2: Chebyshev propagation -> g_TX[g][{0:t1,1:t2}][n][f]
// R5 structure; m-loop unrolled by 2 with float2 A-broadcasts.
// smem floats: A[56*50=2800] | x0[6400] | t1s[6400] | dis[64] | deg[64]
// ============================================================
__global__ __launch_bounds__(256) void k_cheb_prop(const int* __restrict__ EI)
{
    extern __shared__ float sm[];
    float* A   = sm;              // 56 rows x 50 (rows 50..55 zero)
    float* x0  = sm + 2800;
    float* t1s = x0 + NH_;
    float* dis = t1s + NH_;
    int*   deg = (int*)(dis + 64);

    int g = blockIdx.x;
    int b = g / T1, t = g % T1;
    int tid = threadIdx.x;               // 256

    for (int i = tid; i < 2800; i += 256) A[i] = 0.f;
    if (tid < N_) deg[tid] = 0;
    __syncthreads();

    const int* rows = EI + ((size_t)(b*TW + t)*2 + 0)*E_;
    const int* cols = EI + ((size_t)(b*TW + t)*2 + 1)*E_;
    for (int e = tid; e < E_; e += 256) atomicAdd(&deg[rows[e]], 1);
    __syncthreads();
    if (tid < N_) { int d = deg[tid]; dis[tid] = d > 0 ? rsqrtf((float)d) : 0.f; }
    __syncthreads();
    for (int e = tid; e < E_; e += 256) {
        int r = rows[e], c = cols[e];
        atomicAdd(&A[r*N_ + c], -dis[r]*dis[c]);
    }
    // load x0 = T0[g] (50x128)
    {
        const float4* src = (const float4*)(g_T0 + (size_t)g*NH_);
        float4* dst = (float4*)x0;
        for (int i = tid; i < NH_/4; i += 256) dst[i] = src[i];
    }
    __syncthreads();

    const int tx = tid & 31;   // float4 column group
    const int ng = tid >> 5;   // 0..7

    // ---- t1 = A @ x0 ----
    {
        float4 acc[7];
#pragma unroll
        for (int i = 0; i < 7; i++) acc[i] = make_float4(0,0,0,0);
        for (int m = 0; m < N_; m += 2) {
            float4 xv0 = *(const float4*)(x0 + m*H_ + tx*4);
            float4 xv1 = *(const float4*)(x0 + (m+1)*H_ + tx*4);
            float2 a2[7];
#pragma unroll
            for (int i = 0; i < 7; i++)
                a2[i] = *(const float2*)(A + (ng + 8*i)*N_ + m);   // padded rows zero
#pragma unroll
            for (int i = 0; i < 7; i++) {
                acc[i].x += a2[i].x*xv0.x; acc[i].y += a2[i].x*xv0.y;
                acc[i].z += a2[i].x*xv0.z; acc[i].w += a2[i].x*xv0.w;
                acc[i].x += a2[i].y*xv1.x; acc[i].y += a2[i].y*xv1.y;
                acc[i].z += a2[i].y*xv1.z; acc[i].w += a2[i].y*xv1.w;
            }
        }
#pragma unroll
        for (int i = 0; i < 7; i++) {
            int n = ng + 8*i;
            if (n < N_) {
                *(float4*)(t1s + n*H_ + tx*4) = acc[i];
                float4 r = make_float4(rtf(acc[i].x), rtf(acc[i].y), rtf(acc[i].z), rtf(acc[i].w));
                *(float4*)(g_TX + (size_t)g*2*NH_ + n*H_ + tx*4) = r;
            }
        }
    }
    __syncthreads();

    // ---- t2 = 2*A@t1 - x0 ----
    {
        float4 acc[7];
#pragma unroll
        for (int i = 0; i < 7; i++) acc[i] = make_float4(0,0,0,0);
        for (int m = 0; m < N_; m += 2) {
            float4 xv0 = *(const float4*)(t1s + m*H_ + tx*4);
            float4 xv1 = *(const float4*)(t1s + (m+1)*H_ + tx*4);
            float2 a2[7];
#pragma unroll
            for (int i = 0; i < 7; i++)
                a2[i] = *(const float2*)(A + (ng + 8*i)*N_ + m);
#pragma unroll
            for (int i = 0; i < 7; i++) {
                acc[i].x += a2[i].x*xv0.x; acc[i].y += a2[i].x*xv0.y;
                acc[i].z += a2[i].x*xv0.z; acc[i].w += a2[i].x*xv0.w;
                acc[i].x += a2[i].y*xv1.x; acc[i].y += a2[i].y*xv1.y;
                acc[i].z += a2[i].y*xv1.z; acc[i].w += a2[i].y*xv1.w;
            }
        }
#pragma unroll
        for (int i = 0; i < 7; i++) {
            int n = ng + 8*i;
            if (n < N_) {
                float4 xo = *(const float4*)(x0 + n*H_ + tx*4);
                float4 r;
                r.x = rtf(2.f*acc[i].x - xo.x); r.y = rtf(2.f*acc[i].y - xo.y);
                r.z = rtf(2.f*acc[i].z - xo.z); r.w = rtf(2.f*acc[i].w - xo.w);
                *(float4*)(g_TX + (size_t)g*2*NH_ + NH_ + n*H_ + tx*4) = r;
            }
        }
    }
}

// ============================================================
// K3: pack+round tconv2 weights and round cheb weights (merged)
// ============================================================
__global__ void k_prepW(const float* __restrict__ w1, const float* __restrict__ w2,
                        const float* __restrict__ w3, const float* __restrict__ chw)
{
    int i = blockIdx.x*256 + threadIdx.x;
    if (i < 384*64) {
        int kt = i >> 6, co = i & 63;
        g_Wt2[kt*192 + co]       = rtf(w1[i]);
        g_Wt2[kt*192 + 64 + co]  = rtf(w2[i]);
        g_Wt2[kt*192 + 128 + co] = rtf(w3[i]);
    }
    if (i < 384*128) g_Wch[i] = rtf(chw[i]);
}

// ============================================================
// K4: tf32 MMA GEMM, cp.async double-buffered.
// BM=128, BN=64, BK=32, 256 threads (8 warps 4x2)
// MODE 0: A = [T0 | TX] (M_CH x 384), B = g_Wch (384x128), bias+relu -> g_G (rounded)
// MODE 1: A = g_G taps (M_TC x 384),  B = g_Wt2 (384x192), raw -> g_gate
// ============================================================
#define AST 36
#define BST 72
#define NKI 12

#define ISSUE_LOADS(ST, K0) do {                                              \
    int kk_ = (K0) >> 7, fb_ = (K0) & 127;                                    \
    _Pragma("unroll")                                                         \
    for (int j_ = 0; j_ < 4; j_++) {                                          \
        const float* s_;                                                      \
        if (MODE == 0)                                                        \
            s_ = (kk_ == 0) ? (g_T0 + ab0[j_] + fb_ + ac4)                    \
                            : (g_TX + abX[j_] + (size_t)(kk_-1)*NH_ + fb_ + ac4); \
        else                                                                  \
            s_ = g_G + ab0[j_] + (size_t)kk_*NH_ + fb_ + ac4;                 \
        cp16((uint32_t)__cvta_generic_to_shared(&As[ST][arow + j_*32][ac4]), s_); \
    }                                                                         \
    _Pragma("unroll")                                                         \
    for (int j_ = 0; j_ < 2; j_++) {                                          \
        int row_ = brow + j_*16;                                              \
        cp16((uint32_t)__cvta_generic_to_shared(&Bs[ST][row_][bc4]),          \
             Bmat + (size_t)((K0) + row_)*BNS + nb + bc4);                    \
    }                                                                         \
    asm volatile("cp.async.commit_group;");                                   \
} while (0)

template<int MODE>
__global__ __launch_bounds__(256) void k_gemm(const float* __restrict__ bias)
{
    __shared__ float As[2][128][AST];
    __shared__ float Bs[2][32][BST];

    const int tid  = threadIdx.x;
    const int bm   = blockIdx.x;
    const int nb   = blockIdx.y * 64;
    const int warp = tid >> 5, lane = tid & 31;
    const int wm = (warp & 3) * 32, wn = (warp >> 2) * 32;
    const int g4 = lane >> 2, tg = lane & 3;

    const int BNS = (MODE == 0) ? 128 : 192;
    const float* Bmat = (MODE == 0) ? g_Wch : g_Wt2;

    const int arow = tid >> 3, ac4 = (tid & 7) << 2;
    const int brow = tid >> 4, bc4 = (tid & 15) << 2;

    size_t ab0[4], abX[4];
#pragma unroll
    for (int j = 0; j < 4; j++) {
        int R = bm*128 + arow + j*32;
        if (MODE == 0) {
            int g = R / N_, n = R - g*N_;
            ab0[j] = (size_t)g*NH_ + (size_t)n*H_;
            abX[j] = (size_t)g*2*NH_ + (size_t)n*H_;
        } else {
            int b = R / (T2T*N_);
            int rem = R - b*(T2T*N_);
            int t = rem / N_, n = rem - t*N_;
            ab0[j] = ((size_t)(b*T1 + t)*N_ + n)*H_;
            abX[j] = 0;
        }
    }

    float acc[2][4][4];
#pragma unroll
    for (int mt = 0; mt < 2; mt++)
#pragma unroll
        for (int nt = 0; nt < 4; nt++)
#pragma unroll
            for (int q = 0; q < 4; q++) acc[mt][nt][q] = 0.f;

    ISSUE_LOADS(0, 0);

    for (int it = 0; it < NKI; it++) {
        const int st = it & 1;
        if (it + 1 < NKI) {
            ISSUE_LOADS(st ^ 1, (it + 1) * 32);
            asm volatile("cp.async.wait_group 1;");
        } else {
            asm volatile("cp.async.wait_group 0;");
        }
        __syncthreads();

#pragma unroll
        for (int kt = 0; kt < 32; kt += 8) {
            uint32_t af[2][4], bf[4][2];
#pragma unroll
            for (int mt = 0; mt < 2; mt++) {
                int m = wm + mt*16;
                af[mt][0] = __float_as_uint(As[st][m + g4    ][kt + tg]);
                af[mt][1] = __float_as_uint(As[st][m + g4 + 8][kt + tg]);
                af[mt][2] = __float_as_uint(As[st][m + g4    ][kt + tg + 4]);
                af[mt][3] = __float_as_uint(As[st][m + g4 + 8][kt + tg + 4]);
            }
#pragma unroll
            for (int nt = 0; nt < 4; nt++) {
                bf[nt][0] = __float_as_uint(Bs[st][kt + tg    ][wn + nt*8 + g4]);
                bf[nt][1] = __float_as_uint(Bs[st][kt + tg + 4][wn + nt*8 + g4]);
            }
#pragma unroll
            for (int mt = 0; mt < 2; mt++)
#pragma unroll
                for (int nt = 0; nt < 4; nt++)
                    mma_tf32(acc[mt][nt], af[mt], bf[nt]);
        }
        __syncthreads();
    }

    // epilogue
#pragma unroll
    for (int mt = 0; mt < 2; mt++) {
        int r0 = bm*128 + wm + mt*16 + g4;
#pragma unroll
        for (int nt = 0; nt < 4; nt++) {
            int c = nb + wn + nt*8 + tg*2;
            float v0 = acc[mt][nt][0], v1 = acc[mt][nt][1];
            float v2 = acc[mt][nt][2], v3 = acc[mt][nt][3];
            if (MODE == 0) {
                float bx = bias[c], by = bias[c+1];
                v0 += bx; v1 += by; v2 += bx; v3 += by;
                v0 = v0 > 0.f ? rtf(v0) : 0.f; v1 = v1 > 0.f ? rtf(v1) : 0.f;
                v2 = v2 > 0.f ? rtf(v2) : 0.f; v3 = v3 > 0.f ? rtf(v3) : 0.f;
                *(float2*)(g_G + (size_t)r0*128 + c)      = make_float2(v0, v1);
                *(float2*)(g_G + (size_t)(r0+8)*128 + c)  = make_float2(v2, v3);
            } else {
                *(float2*)(g_gate + (size_t)r0*192 + c)     = make_float2(v0, v1);
                *(float2*)(g_gate + (size_t)(r0+8)*192 + c) = make_float2(v2, v3);
            }
        }
    }
}

// ============================================================
// K5: tconv2 gate epilogue: relu(P*sig(Q)+R) -> g_T2
// ============================================================
__global__ void k_tc2epi(const float* __restrict__ b1, const float* __restrict__ b2,
                         const float* __restrict__ b3)
{
    int idx = blockIdx.x*256 + threadIdx.x;      // over M_TC*64
    if (idx >= M_TC*CO_) return;
    int row = idx >> 6, co = idx & 63;
    const float* gr = g_gate + (size_t)row*192;
    float P = gr[co] + b1[co];
    float Q = gr[64 + co] + b2[co];
    float R = gr[128 + co] + b3[co];
    float s = 1.f/(1.f + expf(-Q));
    float o = P*s + R;
    g_T2[idx] = o > 0.f ? o : 0.f;
}

// ============================================================
// K6: BN partial sums  grid(50,16), then finalize
// ============================================================
__global__ void k_bnpart()
{
    int n = blockIdx.x, ch = blockIdx.y;
    int tid = threadIdx.x;                       // 128
    float s = 0.f, s2 = 0.f;
    for (int i = tid; i < 72*64; i += 128) {
        int row = ch*72 + (i >> 6);
        int co = i & 63;
        float v = g_T2[((size_t)row*N_ + n)*CO_ + co];
        s += v; s2 += v*v;
    }
    __shared__ float red[256];
    red[tid] = s; red[128 + tid] = s2;
    __syncthreads();
    for (int st = 64; st > 0; st >>= 1) {
        if (tid < st) { red[tid] += red[tid+st]; red[128+tid] += red[128+tid+st]; }
        __syncthreads();
    }
    if (tid == 0) {
        g_bnpart[(n*16 + ch)*2]     = red[0];
        g_bnpart[(n*16 + ch)*2 + 1] = red[128];
    }
}

__global__ void k_bnfin(const float* __restrict__ gamma, const float* __restrict__ beta)
{
    int n = threadIdx.x;
    if (n >= N_) return;
    float s = 0.f, s2 = 0.f;
    for (int ch = 0; ch < 16; ch++) {
        s  += g_bnpart[(n*16 + ch)*2];
        s2 += g_bnpart[(n*16 + ch)*2 + 1];
    }
    const float TOT = (float)(B_*T2T*CO_);
    float mean = s / TOT;
    float var  = s2 / TOT - mean*mean;
    float rstd = rsqrtf(var + 1e-5f);
    float sc = gamma[n]*rstd;
    g_scale[n] = sc;
    g_shift[n] = beta[n] - mean*sc;
}

// ============================================================
// K7: build V[b][k][j]
// ============================================================
__global__ void k_vprep()
{
    int b = blockIdx.x;
    int j = blockIdx.y*256 + threadIdx.x;
    if (j >= J_) return;
    int n = j / CO_;
    float sc = g_scale[n], sh = g_shift[n];
    const float* base = g_T2 + (size_t)b*T2T*J_ + j;
    float TS = 0.f, v0 = 0.f, v1 = 0.f, v34 = 0.f, v35 = 0.f;
    for (int t = 0; t < T2T; t++) {
        float x = base[(size_t)t*J_]*sc + sh;
        TS += x;
        if (t == 0)  v0 = x;
        if (t == 1)  v1 = x;
        if (t == 34) v34 = x;
        if (t == 35) v35 = x;
    }
    g_V[((size_t)b*3 + 0)*J_ + j] = TS - v34 - v35;
    g_V[((size_t)b*3 + 1)*J_ + j] = TS - v0  - v35;
    g_V[((size_t)b*3 + 2)*J_ + j] = TS - v0  - v1;
}

// ============================================================
// K8: pooled[b,o] = c3b[o] + (1/34)*dot(conv3_w[o], V[b])
// ============================================================
__global__ void k_pooled(const float* __restrict__ c3w, const float* __restrict__ c3b)
{
    int o = blockIdx.x;
    int b = blockIdx.y;
    int tid = threadIdx.x;
    const float* w = c3w + (size_t)o*3*J_;
    const float* v = g_V + (size_t)b*3*J_;
    float s = 0.f;
    for (int i = tid; i < 3*J_; i += 256) s += w[i]*v[i];
    __shared__ float red[256];
    red[tid] = s; __syncthreads();
    for (int st = 128; st > 0; st >>= 1) {
        if (tid < st) red[tid] += red[tid+st];
        __syncthreads();
    }
    if (tid == 0) g_pooled[b*OC3 + o] = c3b[o] + red[0]*(1.f/34.f);
}

// ============================================================
// K9: out[b,j] = f1_b[j] + sum_o pooled[b,o]*f1_w[o,j]
// ============================================================
__global__ void k_fc(const float* __restrict__ f1w, const float* __restrict__ f1b,
                     float* __restrict__ out)
{
    int b = blockIdx.y;
    int j = blockIdx.x*128 + threadIdx.x;
    __shared__ float ps[OC3];
    ps[threadIdx.x] = g_pooled[b*OC3 + threadIdx.x];
    __syncthreads();
    float s = f1b[j];
#pragma unroll 4
    for (int o = 0; o < OC3; o++) s += ps[o]*f1w[(size_t)o*J_ + j];
    out[(size_t)b*J_ + j] = s;
}

// ============================================================
// host launcher
// ============================================================
extern "C" void kernel_launch(void* const* d_in, const int* in_sizes, int n_in,
                              void* d_out, int out_size)
{
    const float *X=0,*w11=0,*b11=0,*w12=0,*b12=0,*w13=0,*b13=0;
    const float *chw=0,*chb=0;
    const float *w21=0,*b21=0,*w22=0,*b22=0,*w23=0,*b23=0;
    const float *gamma=0,*beta=0,*c3w=0,*c3b=0,*f1w=0,*f1b=0;
    const int *ei=0;
    int c768=0, c128=0, c24576=0, c64=0, c50=0;
    for (int i = 0; i < n_in; i++) {
        int s = in_sizes[i];
        const void* p = d_in[i];
        switch (s) {
            case 128000:  X = (const float*)p; break;
            case 2048000: ei = (const int*)p; break;
            case 768:
                if (c768==0) w11=(const float*)p; else if (c768==1) w12=(const float*)p; else w13=(const float*)p;
                c768++; break;
            case 128:
                if (c128==0) b11=(const float*)p; else if (c128==1) b12=(const float*)p;
                else if (c128==2) b13=(const float*)p; else if (c128==3) chb=(const float*)p;
                else c3b=(const float*)p;
                c128++; break;
            case 49152:   chw = (const float*)p; break;
            case 24576:
                if (c24576==0) w21=(const float*)p; else if (c24576==1) w22=(const float*)p; else w23=(const float*)p;
                c24576++; break;
            case 64:
                if (c64==0) b21=(const float*)p; else if (c64==1) b22=(const float*)p; else b23=(const float*)p;
                c64++; break;
            case 50:
                if (c50==0) gamma=(const float*)p; else beta=(const float*)p;
                c50++; break;
            case 1228800: c3w = (const float*)p; break;
            case 409600:  f1w = (const float*)p; break;
            case 3200:    f1b = (const float*)p; break;
            default: break;
        }
    }
    float* out = (float*)d_out;

    static const int PROP_SMEM = (2800 + NH_ + NH_ + 64 + 64) * 4;  // 62.9 KB
    cudaFuncSetAttribute(k_cheb_prop, cudaFuncAttributeMaxDynamicSharedMemorySize, PROP_SMEM);

    k_tconv1   <<<B_*N_, 128>>>(X, w11, b11, w12, b12, w13, b13);
    k_prepW    <<<(384*128 + 255)/256, 256>>>(w21, w22, w23, chw);
    k_cheb_prop<<<NG, 256, PROP_SMEM>>>(ei);
    k_gemm<0>  <<<dim3(M_CH/128, 2), 256>>>(chb);
    k_gemm<1>  <<<dim3(M_TC/128, 3), 256>>>(nullptr);
    k_tc2epi   <<<(M_TC*CO_ + 255)/256, 256>>>(b21, b22, b23);
    k_bnpart   <<<dim3(N_, 16), 128>>>();
    k_bnfin    <<<1, 64>>>(gamma, beta);
    k_vprep    <<<dim3(B_, (J_+255)/256), 256>>>();
    k_pooled   <<<dim3(OC3, B_), 256>>>(c3w, c3b);
    k_fc       <<<dim3(J_/128, B_), 128>>>(f1w, f1b, out);
}

// round 10
// speedup vs baseline: 1.1216x; 1.0956x over previous
#include <cuda_runtime.h>
#include <cuda_bf16.h>
#include <math.h>
#include <stdint.h>

// ---------------- problem constants ----------------
#define B_   32
#define TW   40
#define N_   50
#define CIN  2
#define H_   128
#define CO_  64
#define E_   800
#define T1   38            // after tconv1
#define T2T  36            // after tconv2
#define NG   (B_*T1)       // 1216 graphs
#define J_   (N_*CO_)      // 3200
#define OC3  128           // conv3 out channels
#define M_CH (NG*N_)       // 60800 rows, cheb GEMM
#define M_TC (B_*T2T*N_)   // 57600 rows, tconv2 GEMM
#define NH_  (N_*H_)       // 6400

// ---------------- scratch (static device, no allocation) ----------------
__device__ float g_T0[NG*NH_];              // 7.78M  (tf32-rounded)
__device__ float g_TX[NG*2*NH_];            // 15.6M  [g][k-1][n][f] (tf32-rounded)
__device__ float g_G [NG*NH_];              // 7.78M  (tf32-rounded)
__device__ float g_Wch[384*128];            // rounded cheb weights
__device__ float g_Wt2[384*192];            // packed+rounded tconv2 weights
__device__ float g_T2[(size_t)M_TC*CO_];    // 14.7MB
__device__ float g_V [B_*3*J_];
__device__ float g_bnpart[N_*16*2];
__device__ float g_scale[N_], g_shift[N_];
__device__ float g_pooled[B_*OC3];

// ---------------- helpers ----------------
__device__ __forceinline__ uint32_t f2tf(float f) {
    uint32_t u; asm("cvt.rna.tf32.f32 %0, %1;" : "=r"(u) : "f"(f)); return u;
}
__device__ __forceinline__ float rtf(float f) { return __uint_as_float(f2tf(f)); }
__device__ __forceinline__ void mma_tf32(float* c, const uint32_t* a, const uint32_t* b) {
    asm volatile("mma.sync.aligned.m16n8k8.row.col.f32.tf32.tf32.f32 "
        "{%0,%1,%2,%3}, {%4,%5,%6,%7}, {%8,%9}, {%0,%1,%2,%3};"
        : "+f"(c[0]), "+f"(c[1]), "+f"(c[2]), "+f"(c[3])
        : "r"(a[0]), "r"(a[1]), "r"(a[2]), "r"(a[3]), "r"(b[0]), "r"(b[1]));
}
__device__ __forceinline__ void cp16(uint32_t dst, const void* src) {
    asm volatile("cp.async.cg.shared.global [%0], [%1], 16;" :: "r"(dst), "l"(src));
}

// ============================================================
// K1: tconv1  X(B,40,50,2) -> T0(B,38,50,128), tf32-rounded store
// ============================================================
__global__ void k_tconv1(const float* __restrict__ X,
                         const float* __restrict__ w1, const float* __restrict__ b1,
                         const float* __restrict__ w2, const float* __restrict__ b2,
                         const float* __restrict__ w3, const float* __restrict__ b3)
{
    int bn = blockIdx.x;
    int b = bn / N_, n = bn % N_;
    int h = threadIdx.x;

    __shared__ float xs[TW*CIN];
    for (int i = threadIdx.x; i < TW*CIN; i += blockDim.x) {
        int t = i >> 1, c = i & 1;
        xs[i] = X[((b*TW + t)*N_ + n)*CIN + c];
    }
    float W1[6], W2[6], W3[6];
#pragma unroll
    for (int q = 0; q < 6; q++) {
        W1[q] = w1[q*H_ + h]; W2[q] = w2[q*H_ + h]; W3[q] = w3[q*H_ + h];
    }
    float B1 = b1[h], B2 = b2[h], B3 = b3[h];
    __syncthreads();

    for (int t = 0; t < T1; t++) {
        float P = B1, Q = B2, R = B3;
#pragma unroll
        for (int k = 0; k < 3; k++)
#pragma unroll
            for (int c = 0; c < 2; c++) {
                float v = xs[(t+k)*2 + c];
                int q = k*2 + c;
                P += v*W1[q]; Q += v*W2[q]; R += v*W3[q];
            }
        float s = 1.f/(1.f + expf(-Q));
        float o = P*s + R;
        o = o > 0.f ? o : 0.f;
        g_T0[((size_t)(b*T1 + t)*N_ + n)*H_ + h] = rtf(o);
    }
}

// ============================================================
// K2: Chebyshev propagation -> g_TX[g][{0:t1,1:t2}][n][f]
// (R5-validated structure)
// smem floats: A[56*50=2800] | x0[6400] | t1s[6400] | dis[64] | deg[64]
// ============================================================
__global__ __launch_bounds__(256) void k_cheb_prop(const int* __restrict__ EI)
{
    extern __shared__ float sm[];
    float* A   = sm;              // 56 rows x 50 (rows 50..55 zero)
    float* x0  = sm + 2800;
    float* t1s = x0 + NH_;
    float* dis = t1s + NH_;
    int*   deg = (int*)(dis + 64);

    int g = blockIdx.x;
    int b = g / T1, t = g % T1;
    int tid = threadIdx.x;               // 256

    for (int i = tid; i < 2800; i += 256) A[i] = 0.f;
    if (tid < N_) deg[tid] = 0;
    __syncthreads();

    const int* rows = EI + ((size_t)(b*TW + t)*2 + 0)*E_;
    const int* cols = EI + ((size_t)(b*TW + t)*2 + 1)*E_;
    for (int e = tid; e < E_; e += 256) atomicAdd(&deg[rows[e]], 1);
    __syncthreads();
    if (tid < N_) { int d = deg[tid]; dis[tid] = d > 0 ? rsqrtf((float)d) : 0.f; }
    __syncthreads();
    for (int e = tid; e < E_; e += 256) {
        int r = rows[e], c = cols[e];
        atomicAdd(&A[r*N_ + c], -dis[r]*dis[c]);
    }
    {
        const float4* src = (const float4*)(g_T0 + (size_t)g*NH_);
        float4* dst = (float4*)x0;
        for (int i = tid; i < NH_/4; i += 256) dst[i] = src[i];
    }
    __syncthreads();

    const int tx = tid & 31;   // float4 column group
    const int ng = tid >> 5;   // 0..7

    // ---- t1 = A @ x0 ----
    {
        float4 acc[7];
#pragma unroll
        for (int i = 0; i < 7; i++) acc[i] = make_float4(0,0,0,0);
        for (int m = 0; m < N_; m += 2) {
            float4 xv0 = *(const float4*)(x0 + m*H_ + tx*4);
            float4 xv1 = *(const float4*)(x0 + (m+1)*H_ + tx*4);
            float2 a2[7];
#pragma unroll
            for (int i = 0; i < 7; i++)
                a2[i] = *(const float2*)(A + (ng + 8*i)*N_ + m);
#pragma unroll
            for (int i = 0; i < 7; i++) {
                acc[i].x += a2[i].x*xv0.x; acc[i].y += a2[i].x*xv0.y;
                acc[i].z += a2[i].x*xv0.z; acc[i].w += a2[i].x*xv0.w;
                acc[i].x += a2[i].y*xv1.x; acc[i].y += a2[i].y*xv1.y;
                acc[i].z += a2[i].y*xv1.z; acc[i].w += a2[i].y*xv1.w;
            }
        }
#pragma unroll
        for (int i = 0; i < 7; i++) {
            int n = ng + 8*i;
            if (n < N_) {
                *(float4*)(t1s + n*H_ + tx*4) = acc[i];
                float4 r = make_float4(rtf(acc[i].x), rtf(acc[i].y), rtf(acc[i].z), rtf(acc[i].w));
                *(float4*)(g_TX + (size_t)g*2*NH_ + n*H_ + tx*4) = r;
            }
        }
    }
    __syncthreads();

    // ---- t2 = 2*A@t1 - x0 ----
    {
        float4 acc[7];
#pragma unroll
        for (int i = 0; i < 7; i++) acc[i] = make_float4(0,0,0,0);
        for (int m = 0; m < N_; m += 2) {
            float4 xv0 = *(const float4*)(t1s + m*H_ + tx*4);
            float4 xv1 = *(const float4*)(t1s + (m+1)*H_ + tx*4);
            float2 a2[7];
#pragma unroll
            for (int i = 0; i < 7; i++)
                a2[i] = *(const float2*)(A + (ng + 8*i)*N_ + m);
#pragma unroll
            for (int i = 0; i < 7; i++) {
                acc[i].x += a2[i].x*xv0.x; acc[i].y += a2[i].x*xv0.y;
                acc[i].z += a2[i].x*xv0.z; acc[i].w += a2[i].x*xv0.w;
                acc[i].x += a2[i].y*xv1.x; acc[i].y += a2[i].y*xv1.y;
                acc[i].z += a2[i].y*xv1.z; acc[i].w += a2[i].y*xv1.w;
            }
        }
#pragma unroll
        for (int i = 0; i < 7; i++) {
            int n = ng + 8*i;
            if (n < N_) {
                float4 xo = *(const float4*)(x0 + n*H_ + tx*4);
                float4 r;
                r.x = rtf(2.f*acc[i].x - xo.x); r.y = rtf(2.f*acc[i].y - xo.y);
                r.z = rtf(2.f*acc[i].z - xo.z); r.w = rtf(2.f*acc[i].w - xo.w);
                *(float4*)(g_TX + (size_t)g*2*NH_ + NH_ + n*H_ + tx*4) = r;
            }
        }
    }
}

// ============================================================
// K3: pack+round tconv2 weights and round cheb weights (merged)
// ============================================================
__global__ void k_prepW(const float* __restrict__ w1, const float* __restrict__ w2,
                        const float* __restrict__ w3, const float* __restrict__ chw)
{
    int i = blockIdx.x*256 + threadIdx.x;
    if (i < 384*64) {
        int kt = i >> 6, co = i & 63;
        g_Wt2[kt*192 + co]       = rtf(w1[i]);
        g_Wt2[kt*192 + 64 + co]  = rtf(w2[i]);
        g_Wt2[kt*192 + 128 + co] = rtf(w3[i]);
    }
    if (i < 384*128) g_Wch[i] = rtf(chw[i]);
}

// ============================================================
// K4a: cheb GEMM. BM=128, BN=128 (full N, single y), BK=32.
// 256 threads, 8 warps (4 M x 2 N), warp tile 32x64.
// A = [T0 | TX] (M_CH x 384), B = g_Wch (384x128), bias+relu -> g_G
// ============================================================
__global__ __launch_bounds__(256) void k_gemm0(const float* __restrict__ bias)
{
    __shared__ float As[2][128][36];
    __shared__ float Bs[2][32][136];

    const int tid  = threadIdx.x;
    const int bm   = blockIdx.x;
    const int warp = tid >> 5, lane = tid & 31;
    const int wm = (warp & 3) * 32, wn = (warp >> 2) * 64;
    const int g4 = lane >> 2, tg = lane & 3;

    const int arow = tid >> 3, ac4 = (tid & 7) << 2;   // A: rows arow+32j, 32 cols
    const int brow = tid >> 5, bc4 = (tid & 31) << 2;  // B: rows brow+8j, 128 cols

    size_t ab0[4], abX[4];
#pragma unroll
    for (int j = 0; j < 4; j++) {
        int R = bm*128 + arow + j*32;
        int g = R / N_, n = R - g*N_;
        ab0[j] = (size_t)g*NH_ + (size_t)n*H_;
        abX[j] = (size_t)g*2*NH_ + (size_t)n*H_;
    }

    float acc[2][8][4];
#pragma unroll
    for (int mt = 0; mt < 2; mt++)
#pragma unroll
        for (int nt = 0; nt < 8; nt++)
#pragma unroll
            for (int q = 0; q < 4; q++) acc[mt][nt][q] = 0.f;

#define G0_LOADS(ST, K0) do {                                                  \
    int kk_ = (K0) >> 7, fb_ = (K0) & 127;                                     \
    _Pragma("unroll")                                                          \
    for (int j_ = 0; j_ < 4; j_++) {                                           \
        const float* s_ = (kk_ == 0) ? (g_T0 + ab0[j_] + fb_ + ac4)            \
                        : (g_TX + abX[j_] + (size_t)(kk_-1)*NH_ + fb_ + ac4);  \
        cp16((uint32_t)__cvta_generic_to_shared(&As[ST][arow + j_*32][ac4]), s_); \
    }                                                                          \
    _Pragma("unroll")                                                          \
    for (int j_ = 0; j_ < 4; j_++) {                                           \
        int row_ = brow + j_*8;                                                \
        cp16((uint32_t)__cvta_generic_to_shared(&Bs[ST][row_][bc4]),           \
             g_Wch + (size_t)((K0) + row_)*128 + bc4);                         \
    }                                                                          \
    asm volatile("cp.async.commit_group;");                                    \
} while (0)

    G0_LOADS(0, 0);
    for (int it = 0; it < 12; it++) {
        const int st = it & 1;
        if (it + 1 < 12) { G0_LOADS(st ^ 1, (it + 1) * 32); asm volatile("cp.async.wait_group 1;"); }
        else             { asm volatile("cp.async.wait_group 0;"); }
        __syncthreads();

#pragma unroll
        for (int kt = 0; kt < 32; kt += 8) {
            uint32_t af[2][4], bf[8][2];
#pragma unroll
            for (int mt = 0; mt < 2; mt++) {
                int m = wm + mt*16;
                af[mt][0] = __float_as_uint(As[st][m + g4    ][kt + tg]);
                af[mt][1] = __float_as_uint(As[st][m + g4 + 8][kt + tg]);
                af[mt][2] = __float_as_uint(As[st][m + g4    ][kt + tg + 4]);
                af[mt][3] = __float_as_uint(As[st][m + g4 + 8][kt + tg + 4]);
            }
#pragma unroll
            for (int nt = 0; nt < 8; nt++) {
                bf[nt][0] = __float_as_uint(Bs[st][kt + tg    ][wn + nt*8 + g4]);
                bf[nt][1] = __float_as_uint(Bs[st][kt + tg + 4][wn + nt*8 + g4]);
            }
#pragma unroll
            for (int mt = 0; mt < 2; mt++)
#pragma unroll
                for (int nt = 0; nt < 8; nt++)
                    mma_tf32(acc[mt][nt], af[mt], bf[nt]);
        }
        __syncthreads();
    }
#undef G0_LOADS

#pragma unroll
    for (int mt = 0; mt < 2; mt++) {
        int r0 = bm*128 + wm + mt*16 + g4;
#pragma unroll
        for (int nt = 0; nt < 8; nt++) {
            int c = wn + nt*8 + tg*2;
            float bx = bias[c], by = bias[c+1];
            float v0 = acc[mt][nt][0] + bx, v1 = acc[mt][nt][1] + by;
            float v2 = acc[mt][nt][2] + bx, v3 = acc[mt][nt][3] + by;
            v0 = v0 > 0.f ? rtf(v0) : 0.f; v1 = v1 > 0.f ? rtf(v1) : 0.f;
            v2 = v2 > 0.f ? rtf(v2) : 0.f; v3 = v3 > 0.f ? rtf(v3) : 0.f;
            *(float2*)(g_G + (size_t)r0*128 + c)     = make_float2(v0, v1);
            *(float2*)(g_G + (size_t)(r0+8)*128 + c) = make_float2(v2, v3);
        }
    }
}

// ============================================================
// K4b: tconv2 GEMM + fused gate epilogue.  BM=64, BN=192, BK=32.
// 256 threads, 8 warps (2 M x 4 N), warp tile 32x48.
// A = g_G taps (M_TC x 384), B = g_Wt2 (384x192) -> relu(P*sig(Q)+R) -> g_T2
// smem reused as 64x200 staging buffer for the cross-warp epilogue.
// ============================================================
#define G1_ASZ (2*64*36)      // 4608
#define G1_BSZ (2*32*200)     // 12800
__global__ __launch_bounds__(256) void k_gemm1(const float* __restrict__ b1,
                                               const float* __restrict__ b2,
                                               const float* __restrict__ b3)
{
    __shared__ float smr[G1_ASZ + G1_BSZ];   // 69,632 B
    float* As = smr;                          // [st][r][c] st*2304 + r*36 + c
    float* Bs = smr + G1_ASZ;                 // [st][r][c] st*6400 + r*200 + c

    const int tid  = threadIdx.x;
    const int bm   = blockIdx.x;
    const int warp = tid >> 5, lane = tid & 31;
    const int wm = (warp & 1) * 32, wn = (warp >> 1) * 48;
    const int g4 = lane >> 2, tg = lane & 3;

    const int arow = tid >> 3, ac4 = (tid & 7) << 2;   // A rows arow+32j (j=0,1)
    const int brow = tid >> 4, bc4 = (tid & 15) << 2;  // B rows brow+16j, cols bc4+64q

    size_t ab0[2];
#pragma unroll
    for (int j = 0; j < 2; j++) {
        int R = bm*64 + arow + j*32;
        int b = R / (T2T*N_);
        int rem = R - b*(T2T*N_);
        int t = rem / N_, n = rem - t*N_;
        ab0[j] = ((size_t)(b*T1 + t)*N_ + n)*H_;
    }

    float acc[2][6][4];
#pragma unroll
    for (int mt = 0; mt < 2; mt++)
#pragma unroll
        for (int nt = 0; nt < 6; nt++)
#pragma unroll
            for (int q = 0; q < 4; q++) acc[mt][nt][q] = 0.f;

#define G1_LOADS(ST, K0) do {                                                  \
    int kk_ = (K0) >> 7, fb_ = (K0) & 127;                                     \
    _Pragma("unroll")                                                          \
    for (int j_ = 0; j_ < 2; j_++)                                             \
        cp16((uint32_t)__cvta_generic_to_shared(As + (ST)*2304 + (arow + j_*32)*36 + ac4), \
             g_G + ab0[j_] + (size_t)kk_*NH_ + fb_ + ac4);                     \
    _Pragma("unroll")                                                          \
    for (int j_ = 0; j_ < 2; j_++)                                             \
        _Pragma("unroll")                                                      \
        for (int q_ = 0; q_ < 3; q_++) {                                       \
            int row_ = brow + j_*16;                                           \
            cp16((uint32_t)__cvta_generic_to_shared(Bs + (ST)*6400 + row_*200 + bc4 + q_*64), \
                 g_Wt2 + (size_t)((K0) + row_)*192 + bc4 + q_*64);             \
        }                                                                      \
    asm volatile("cp.async.commit_group;");                                    \
} while (0)

    G1_LOADS(0, 0);
    for (int it = 0; it < 12; it++) {
        const int st = it & 1;
        if (it + 1 < 12) { G1_LOADS(st ^ 1, (it + 1) * 32); asm volatile("cp.async.wait_group 1;"); }
        else             { asm volatile("cp.async.wait_group 0;"); }
        __syncthreads();

#pragma unroll
        for (int kt = 0; kt < 32; kt += 8) {
            uint32_t af[2][4], bf[6][2];
#pragma unroll
            for (int mt = 0; mt < 2; mt++) {
                int m = wm + mt*16;
                af[mt][0] = __float_as_uint(As[st*2304 + (m + g4    )*36 + kt + tg]);
                af[mt][1] = __float_as_uint(As[st*2304 + (m + g4 + 8)*36 + kt + tg]);
                af[mt][2] = __float_as_uint(As[st*2304 + (m + g4    )*36 + kt + tg + 4]);
                af[mt][3] = __float_as_uint(As[st*2304 + (m + g4 + 8)*36 + kt + tg + 4]);
            }
#pragma unroll
            for (int nt = 0; nt < 6; nt++) {
                bf[nt][0] = __float_as_uint(Bs[st*6400 + (kt + tg    )*200 + wn + nt*8 + g4]);
                bf[nt][1] = __float_as_uint(Bs[st*6400 + (kt + tg + 4)*200 + wn + nt*8 + g4]);
            }
#pragma unroll
            for (int mt = 0; mt < 2; mt++)
#pragma unroll
                for (int nt = 0; nt < 6; nt++)
                    mma_tf32(acc[mt][nt], af[mt], bf[nt]);
        }
        __syncthreads();
    }
#undef G1_LOADS

    // stage accumulators to smem (reuse mainloop buffers), stride 200
    float* SB = smr;
#pragma unroll
    for (int mt = 0; mt < 2; mt++) {
#pragma unroll
        for (int nt = 0; nt < 6; nt++) {
            int c = wn + nt*8 + tg*2;
            int r0 = wm + mt*16 + g4;
            *(float2*)(SB + r0*200 + c)     = make_float2(acc[mt][nt][0], acc[mt][nt][1]);
            *(float2*)(SB + (r0+8)*200 + c) = make_float2(acc[mt][nt][2], acc[mt][nt][3]);
        }
    }
    __syncthreads();

    // fused gate epilogue: 64 rows x 64 cols
    for (int idx = tid; idx < 64*64; idx += 256) {
        int r = idx >> 6, co = idx & 63;
        float P = SB[r*200 + co]       + b1[co];
        float Q = SB[r*200 + 64 + co]  + b2[co];
        float R = SB[r*200 + 128 + co] + b3[co];
        float s = 1.f/(1.f + expf(-Q));
        float o = P*s + R;
        g_T2[(size_t)(bm*64 + r)*CO_ + co] = o > 0.f ? o : 0.f;
    }
}

// ============================================================
// K6: BN partial sums  grid(50,16), then finalize
// ============================================================
__global__ void k_bnpart()
{
    int n = blockIdx.x, ch = blockIdx.y;
    int tid = threadIdx.x;                       // 128
    float s = 0.f, s2 = 0.f;
    for (int i = tid; i < 72*64; i += 128) {
        int row = ch*72 + (i >> 6);
        int co = i & 63;
        float v = g_T2[((size_t)row*N_ + n)*CO_ + co];
        s += v; s2 += v*v;
    }
    __shared__ float red[256];
    red[tid] = s; red[128 + tid] = s2;
    __syncthreads();
    for (int st = 64; st > 0; st >>= 1) {
        if (tid < st) { red[tid] += red[tid+st]; red[128+tid] += red[128+tid+st]; }
        __syncthreads();
    }
    if (tid == 0) {
        g_bnpart[(n*16 + ch)*2]     = red[0];
        g_bnpart[(n*16 + ch)*2 + 1] = red[128];
    }
}

__global__ void k_bnfin(const float* __restrict__ gamma, const float* __restrict__ beta)
{
    int n = threadIdx.x;
    if (n >= N_) return;
    float s = 0.f, s2 = 0.f;
    for (int ch = 0; ch < 16; ch++) {
        s  += g_bnpart[(n*16 + ch)*2];
        s2 += g_bnpart[(n*16 + ch)*2 + 1];
    }
    const float TOT = (float)(B_*T2T*CO_);
    float mean = s / TOT;
    float var  = s2 / TOT - mean*mean;
    float rstd = rsqrtf(var + 1e-5f);
    float sc = gamma[n]*rstd;
    g_scale[n] = sc;
    g_shift[n] = beta[n] - mean*sc;
}

// ============================================================
// K7: build V[b][k][j]
// ============================================================
__global__ void k_vprep()
{
    int b = blockIdx.x;
    int j = blockIdx.y*256 + threadIdx.x;
    if (j >= J_) return;
    int n = j / CO_;
    float sc = g_scale[n], sh = g_shift[n];
    const float* base = g_T2 + (size_t)b*T2T*J_ + j;
    float TS = 0.f, v0 = 0.f, v1 = 0.f, v34 = 0.f, v35 = 0.f;
    for (int t = 0; t < T2T; t++) {
        float x = base[(size_t)t*J_]*sc + sh;
        TS += x;
        if (t == 0)  v0 = x;
        if (t == 1)  v1 = x;
        if (t == 34) v34 = x;
        if (t == 35) v35 = x;
    }
    g_V[((size_t)b*3 + 0)*J_ + j] = TS - v34 - v35;
    g_V[((size_t)b*3 + 1)*J_ + j] = TS - v0  - v35;
    g_V[((size_t)b*3 + 2)*J_ + j] = TS - v0  - v1;
}

// ============================================================
// K8: pooled[b,o] = c3b[o] + (1/34)*dot(conv3_w[o], V[b])
// ============================================================
__global__ void k_pooled(const float* __restrict__ c3w, const float* __restrict__ c3b)
{
    int o = blockIdx.x;
    int b = blockIdx.y;
    int tid = threadIdx.x;
    const float* w = c3w + (size_t)o*3*J_;
    const float* v = g_V + (size_t)b*3*J_;
    float s = 0.f;
    for (int i = tid; i < 3*J_; i += 256) s += w[i]*v[i];
    __shared__ float red[256];
    red[tid] = s; __syncthreads();
    for (int st = 128; st > 0; st >>= 1) {
        if (tid < st) red[tid] += red[tid+st];
        __syncthreads();
    }
    if (tid == 0) g_pooled[b*OC3 + o] = c3b[o] + red[0]*(1.f/34.f);
}

// ============================================================
// K9: out[b,j] = f1_b[j] + sum_o pooled[b,o]*f1_w[o,j]
// ============================================================
__global__ void k_fc(const float* __restrict__ f1w, const float* __restrict__ f1b,
                     float* __restrict__ out)
{
    int b = blockIdx.y;
    int j = blockIdx.x*128 + threadIdx.x;
    __shared__ float ps[OC3];
    ps[threadIdx.x] = g_pooled[b*OC3 + threadIdx.x];
    __syncthreads();
    float s = f1b[j];
#pragma unroll 4
    for (int o = 0; o < OC3; o++) s += ps[o]*f1w[(size_t)o*J_ + j];
    out[(size_t)b*J_ + j] = s;
}

// ============================================================
// host launcher
// ============================================================
extern "C" void kernel_launch(void* const* d_in, const int* in_sizes, int n_in,
                              void* d_out, int out_size)
{
    const float *X=0,*w11=0,*b11=0,*w12=0,*b12=0,*w13=0,*b13=0;
    const float *chw=0,*chb=0;
    const float *w21=0,*b21=0,*w22=0,*b22=0,*w23=0,*b23=0;
    const float *gamma=0,*beta=0,*c3w=0,*c3b=0,*f1w=0,*f1b=0;
    const int *ei=0;
    int c768=0, c128=0, c24576=0, c64=0, c50=0;
    for (int i = 0; i < n_in; i++) {
        int s = in_sizes[i];
        const void* p = d_in[i];
        switch (s) {
            case 128000:  X = (const float*)p; break;
            case 2048000: ei = (const int*)p; break;
            case 768:
                if (c768==0) w11=(const float*)p; else if (c768==1) w12=(const float*)p; else w13=(const float*)p;
                c768++; break;
            case 128:
                if (c128==0) b11=(const float*)p; else if (c128==1) b12=(const float*)p;
                else if (c128==2) b13=(const float*)p; else if (c128==3) chb=(const float*)p;
                else c3b=(const float*)p;
                c128++; break;
            case 49152:   chw = (const float*)p; break;
            case 24576:
                if (c24576==0) w21=(const float*)p; else if (c24576==1) w22=(const float*)p; else w23=(const float*)p;
                c24576++; break;
            case 64:
                if (c64==0) b21=(const float*)p; else if (c64==1) b22=(const float*)p; else b23=(const float*)p;
                c64++; break;
            case 50:
                if (c50==0) gamma=(const float*)p; else beta=(const float*)p;
                c50++; break;
            case 1228800: c3w = (const float*)p; break;
            case 409600:  f1w = (const float*)p; break;
            case 3200:    f1b = (const float*)p; break;
            default: break;
        }
    }
    float* out = (float*)d_out;

    static const int PROP_SMEM = (2800 + NH_ + NH_ + 64 + 64) * 4;  // 62.9 KB
    cudaFuncSetAttribute(k_cheb_prop, cudaFuncAttributeMaxDynamicSharedMemorySize, PROP_SMEM);

    k_tconv1   <<<B_*N_, 128>>>(X, w11, b11, w12, b12, w13, b13);
    k_prepW    <<<(384*128 + 255)/256, 256>>>(w21, w22, w23, chw);
    k_cheb_prop<<<NG, 256, PROP_SMEM>>>(ei);
    k_gemm0    <<<M_CH/128, 256>>>(chb);
    k_gemm1    <<<M_TC/64, 256>>>(b21, b22, b23);
    k_bnpart   <<<dim3(N_, 16), 128>>>();
    k_bnfin    <<<1, 64>>>(gamma, beta);
    k_vprep    <<<dim3(B_, (J_+255)/256), 256>>>();
    k_pooled   <<<dim3(OC3, B_), 256>>>(c3w, c3b);
    k_fc       <<<dim3(J_/128, B_), 128>>>(f1w, f1b, out);
}